// round 3
// baseline (speedup 1.0000x reference)
#include <cuda_runtime.h>

#define NN 100000
#define EE 400000
#define D4 64          // 256 floats = 64 float4 per row
#define SS 10000

// ---------------- static scratch (no runtime allocation) ----------------
__device__ int    g_deg[2][NN];
__device__ int    g_cursor[2][NN];
__device__ int    g_rowptr[2][NN + 1];
__device__ int    g_adj[2][2 * EE];
__device__ float  g_dinv[2][NN];
__device__ float4 g_b0[2][(size_t)NN * D4];   // g = h * dinv   (layer input)
__device__ float4 g_b1[2][(size_t)NN * D4];   // g1 after layer 1

// ---------------- helpers ----------------
__device__ __forceinline__ void acc4(float4& a, const float4& b) {
    a.x += b.x; a.y += b.y; a.z += b.z; a.w += b.w;
}
__device__ __forceinline__ float4 scl4(const float4& a, float s) {
    float4 r; r.x = a.x * s; r.y = a.y * s; r.z = a.z * s; r.w = a.w * s; return r;
}

// ---------------- setup kernels ----------------
__global__ void k_zero() {
    int i = blockIdx.x * 256 + threadIdx.x;
    if (i < 2 * NN) ((int*)g_deg)[i] = 0;
}

__global__ void k_count(const int2* __restrict__ esr, const int2* __restrict__ etg) {
    int i = blockIdx.x * 256 + threadIdx.x;
    if (i >= 2 * EE) return;
    int side = i >= EE;
    int j = i - side * EE;
    int2 ab = side ? etg[j] : esr[j];
    atomicAdd(&g_deg[side][ab.x], 1);
    atomicAdd(&g_deg[side][ab.y], 1);
}

// single block per side: warp-shuffle based inclusive scan over tiles of 1024
__global__ void k_scan() {
    int side = blockIdx.x;
    __shared__ int warp_sums[32];
    __shared__ int s_carry;
    int tid = threadIdx.x, lane = tid & 31, wid = tid >> 5;
    if (tid == 0) s_carry = 0;
    __syncthreads();
    for (int base = 0; base < NN; base += 1024) {
        int i = base + tid;
        int v = (i < NN) ? g_deg[side][i] : 0;
        int x = v;
        #pragma unroll
        for (int off = 1; off < 32; off <<= 1) {
            int t = __shfl_up_sync(0xffffffffu, x, off);
            if (lane >= off) x += t;
        }
        if (lane == 31) warp_sums[wid] = x;
        __syncthreads();
        if (wid == 0) {
            int y = warp_sums[lane];
            #pragma unroll
            for (int off = 1; off < 32; off <<= 1) {
                int t = __shfl_up_sync(0xffffffffu, y, off);
                if (lane >= off) y += t;
            }
            warp_sums[lane] = y;
        }
        __syncthreads();
        int incl  = x + (wid ? warp_sums[wid - 1] : 0);
        int total = warp_sums[31];
        if (i < NN) {
            int off = s_carry + incl - v;   // exclusive
            g_rowptr[side][i] = off;
            g_cursor[side][i] = off;
            g_dinv[side][i]   = rsqrtf((float)(v + 1));  // +1 = self loop
        }
        __syncthreads();
        if (tid == 0) s_carry += total;
        __syncthreads();
    }
    if (threadIdx.x == 0) g_rowptr[side][NN] = 2 * EE;
}

__global__ void k_fill(const int2* __restrict__ esr, const int2* __restrict__ etg) {
    int i = blockIdx.x * 256 + threadIdx.x;
    if (i >= 2 * EE) return;
    int side = i >= EE;
    int j = i - side * EE;
    int2 ab = side ? etg[j] : esr[j];
    int p = atomicAdd(&g_cursor[side][ab.x], 1);
    g_adj[side][p] = ab.y;
    int q = atomicAdd(&g_cursor[side][ab.y], 1);
    g_adj[side][q] = ab.x;
}

// g0 = feats * dinv[row]
__global__ void k_scale(const float4* __restrict__ fsr, const float4* __restrict__ ftg) {
    int i = blockIdx.x * 256 + threadIdx.x;
    if (i >= 2 * NN * D4) return;
    int side = i >= NN * D4;
    int j = i - side * NN * D4;
    float s = g_dinv[side][j >> 6];
    float4 x = side ? ftg[j] : fsr[j];
    g_b0[side][j] = scl4(x, s);
}

// ---------------- aggregation: one warp per node, 8 floats / lane --------
// FINAL=false: out g1[v] = relu(dinv[v]*acc) * dinv[v]  -> g_b1
// FINAL=true : out row   = l2normalize(dinv[v]*acc)     -> d_out ent region
template <bool FINAL>
__global__ void k_layer(int side, float4* out) {
    int gw = (blockIdx.x * blockDim.x + threadIdx.x) >> 5;
    if (gw >= NN) return;
    int v = gw;
    int lane = threadIdx.x & 31;

    const float4* __restrict__ gin = FINAL ? g_b1[side] : g_b0[side];
    const float4* row = gin + (size_t)v * D4;
    float4 a0 = __ldg(row + lane);
    float4 a1 = __ldg(row + lane + 32);

    int s = g_rowptr[side][v];
    int e = g_rowptr[side][v + 1];
    const int* __restrict__ adj = g_adj[side];
    for (int p = s; p < e; p++) {
        int u = __ldg(adj + p);
        const float4* ru = gin + (size_t)u * D4;
        float4 x0 = __ldg(ru + lane);
        float4 x1 = __ldg(ru + lane + 32);
        acc4(a0, x0);
        acc4(a1, x1);
    }

    float dv = g_dinv[side][v];
    if (!FINAL) {
        float4 r0, r1;
        r0.x = fmaxf(dv * a0.x, 0.f) * dv;  r0.y = fmaxf(dv * a0.y, 0.f) * dv;
        r0.z = fmaxf(dv * a0.z, 0.f) * dv;  r0.w = fmaxf(dv * a0.w, 0.f) * dv;
        r1.x = fmaxf(dv * a1.x, 0.f) * dv;  r1.y = fmaxf(dv * a1.y, 0.f) * dv;
        r1.z = fmaxf(dv * a1.z, 0.f) * dv;  r1.w = fmaxf(dv * a1.w, 0.f) * dv;
        float4* o = g_b1[side] + (size_t)v * D4;
        o[lane] = r0;
        o[lane + 32] = r1;
    } else {
        float4 r0 = scl4(a0, dv);
        float4 r1 = scl4(a1, dv);
        float ss = r0.x * r0.x + r0.y * r0.y + r0.z * r0.z + r0.w * r0.w
                 + r1.x * r1.x + r1.y * r1.y + r1.z * r1.z + r1.w * r1.w;
        #pragma unroll
        for (int off = 16; off; off >>= 1) ss += __shfl_xor_sync(0xffffffffu, ss, off);
        float inv = 1.0f / fmaxf(sqrtf(ss), 1e-12f);
        r0 = scl4(r0, inv);
        r1 = scl4(r1, inv);
        size_t base = (size_t)(2 * SS) * D4 + (size_t)side * NN * D4 + (size_t)v * D4;
        out[base + lane]      = r0;
        out[base + lane + 32] = r1;
    }
}

// seed gather (copies rows out of d_out's ent regions into the seed regions)
__global__ void k_seed(const int* __restrict__ ssr, const int* __restrict__ stg,
                       float4* out) {
    int i = blockIdx.x * 256 + threadIdx.x;
    if (i >= 2 * SS * D4) return;
    int row = i >> 6, c = i & 63;
    int side = row >= SS;
    int s = row - side * SS;
    int node = side ? stg[s] : ssr[s];
    size_t src = (size_t)(2 * SS) * D4 + (size_t)side * NN * D4 + (size_t)node * D4 + c;
    out[i] = out[src];
}

// ---------------- launch ----------------
extern "C" void kernel_launch(void* const* d_in, const int* in_sizes, int n_in,
                              void* d_out, int out_size) {
    const float4* fsr = (const float4*)d_in[0];
    const float4* ftg = (const float4*)d_in[1];
    const int2*   esr = (const int2*)d_in[2];
    const int2*   etg = (const int2*)d_in[3];
    const int*    ssr = (const int*)d_in[4];
    const int*    stg = (const int*)d_in[5];
    float4* out = (float4*)d_out;

    k_zero<<<(2 * NN + 255) / 256, 256>>>();
    k_count<<<(2 * EE + 255) / 256, 256>>>(esr, etg);
    k_scan<<<2, 1024>>>();
    k_fill<<<(2 * EE + 255) / 256, 256>>>(esr, etg);
    k_scale<<<(2 * NN * D4 + 255) / 256, 256>>>(fsr, ftg);

    // sides sequential on purpose: keeps each 102 MB gather table L2-resident
    int lb = (NN * 32 + 255) / 256;   // one warp per node
    k_layer<false><<<lb, 256>>>(0, nullptr);
    k_layer<false><<<lb, 256>>>(1, nullptr);
    k_layer<true><<<lb, 256>>>(0, out);
    k_layer<true><<<lb, 256>>>(1, out);

    k_seed<<<(2 * SS * D4 + 255) / 256, 256>>>(ssr, stg, out);
}

// round 4
// speedup vs baseline: 1.6879x; 1.6879x over previous
#include <cuda_runtime.h>
#include <cuda_fp16.h>
#include <cstring>

#define NN 100000
#define EE 400000
#define D4 64          // 256 floats = 64 float4 per row
#define SS 10000
#define NT 98          // ceil(NN/1024) scan tiles per side

// ---------------- static scratch (no runtime allocation) ----------------
__device__ int    g_deg[2][NN];
__device__ int    g_cursor[2][NN];
__device__ int    g_rowptr[2][NN + 1];
__device__ int    g_adj[2][2 * EE];
__device__ float  g_dinv[2][NN];
__device__ int    g_tileoff[2][NT];
__device__ uint2  g_h0[2][(size_t)NN * 64];   // fp16 node table, layer-1 input (512B/row)
__device__ uint2  g_h1[2][(size_t)NN * 64];   // fp16 node table, layer-2 input

// ---------------- half2 <-> float helpers ----------------
__device__ __forceinline__ float2 u2f(unsigned int u) {
    __half2 h; memcpy(&h, &u, 4); return __half22float2(h);
}
__device__ __forceinline__ unsigned int f2u(float a, float b) {
    __half2 h = __floats2half2_rn(a, b); unsigned int u; memcpy(&u, &h, 4); return u;
}
__device__ __forceinline__ void unpack_add(float* a, uint2 v) {
    float2 f0 = u2f(v.x), f1 = u2f(v.y);
    a[0] += f0.x; a[1] += f0.y; a[2] += f1.x; a[3] += f1.y;
}

// ---------------- setup kernels ----------------
__global__ void k_zero() {
    int i = blockIdx.x * 256 + threadIdx.x;
    if (i < 2 * NN) ((int*)g_deg)[i] = 0;
}

__global__ void k_count(const int2* __restrict__ esr, const int2* __restrict__ etg) {
    int i = blockIdx.x * 256 + threadIdx.x;
    if (i >= 2 * EE) return;
    int side = i >= EE;
    int j = i - side * EE;
    int2 ab = side ? etg[j] : esr[j];
    atomicAdd(&g_deg[side][ab.x], 1);
    atomicAdd(&g_deg[side][ab.y], 1);
}

// scan stage 1: per-tile (1024 elems) degree sums
__global__ void k_s1() {
    __shared__ int ws[8];
    int b = blockIdx.x;
    int side = b >= NT;
    int t = b - side * NT;
    int tid = threadIdx.x;
    int base = t * 1024 + tid * 4;
    int s = 0;
    #pragma unroll
    for (int k = 0; k < 4; k++) {
        int i = base + k;
        if (i < NN) s += g_deg[side][i];
    }
    #pragma unroll
    for (int off = 16; off; off >>= 1) s += __shfl_xor_sync(0xffffffffu, s, off);
    if ((tid & 31) == 0) ws[tid >> 5] = s;
    __syncthreads();
    if (tid == 0) {
        int tot = 0;
        #pragma unroll
        for (int w = 0; w < 8; w++) tot += ws[w];
        g_tileoff[side][t] = tot;   // temporarily holds tile sums
    }
}

// scan stage 2: exclusive scan of tile sums (trivial size: 2 x 98)
__global__ void k_s2() {
    int side = threadIdx.x;
    if (side >= 2) return;
    int acc = 0;
    for (int t = 0; t < NT; t++) {
        int v = g_tileoff[side][t];
        g_tileoff[side][t] = acc;
        acc += v;
    }
}

// scan stage 3: in-tile exclusive scan + tile offset -> rowptr/cursor/dinv
__global__ void k_s3() {
    __shared__ int ws[8];
    int b = blockIdx.x;
    int side = b >= NT;
    int t = b - side * NT;
    int tid = threadIdx.x, lane = tid & 31, wid = tid >> 5;
    int base = t * 1024 + tid * 4;
    int v[4];
    #pragma unroll
    for (int k = 0; k < 4; k++) {
        int i = base + k;
        v[k] = (i < NN) ? g_deg[side][i] : 0;
    }
    int tsum = v[0] + v[1] + v[2] + v[3];
    // warp inclusive scan of thread sums
    int x = tsum;
    #pragma unroll
    for (int off = 1; off < 32; off <<= 1) {
        int tt = __shfl_up_sync(0xffffffffu, x, off);
        if (lane >= off) x += tt;
    }
    if (lane == 31) ws[wid] = x;
    __syncthreads();
    int woff = 0;
    if (wid > 0) {
        #pragma unroll
        for (int w = 0; w < 7; w++) if (w < wid) woff += ws[w];
    }
    int off = g_tileoff[side][t] + woff + (x - tsum);   // exclusive offset of this thread's chunk
    #pragma unroll
    for (int k = 0; k < 4; k++) {
        int i = base + k;
        if (i < NN) {
            g_rowptr[side][i] = off;
            g_cursor[side][i] = off;
            g_dinv[side][i]   = rsqrtf((float)(v[k] + 1));  // +1 = self loop
        }
        off += v[k];
    }
    if (t == 0 && tid == 0) g_rowptr[side][NN] = 2 * EE;
}

__global__ void k_fill(const int2* __restrict__ esr, const int2* __restrict__ etg) {
    int i = blockIdx.x * 256 + threadIdx.x;
    if (i >= 2 * EE) return;
    int side = i >= EE;
    int j = i - side * EE;
    int2 ab = side ? etg[j] : esr[j];
    int p = atomicAdd(&g_cursor[side][ab.x], 1);
    g_adj[side][p] = ab.y;
    int q = atomicAdd(&g_cursor[side][ab.y], 1);
    g_adj[side][q] = ab.x;
}

// g0 = fp16(feats * dinv[row]) : one float4 in -> one uint2 (4 halfs) out
__global__ void k_scale(const float4* __restrict__ fsr, const float4* __restrict__ ftg) {
    int i = blockIdx.x * 256 + threadIdx.x;
    if (i >= 2 * NN * D4) return;
    int side = i >= NN * D4;
    int j = i - side * NN * D4;
    float s = g_dinv[side][j >> 6];
    float4 x = side ? ftg[j] : fsr[j];
    uint2 o;
    o.x = f2u(x.x * s, x.y * s);
    o.y = f2u(x.z * s, x.w * s);
    g_h0[side][j] = o;
}

// ---------------- aggregation: one warp per node, 8 floats / lane --------
// lane l holds float columns [4l..4l+3] and [128+4l..128+4l+3]
// FINAL=false: g1[v] = fp16( relu(dinv[v]*acc) * dinv[v] )  -> g_h1
// FINAL=true : row    = l2normalize(dinv[v]*acc)            -> d_out ent region (fp32)
template <bool FINAL>
__global__ void k_layer(int side, float4* out) {
    int gw = (blockIdx.x * blockDim.x + threadIdx.x) >> 5;
    if (gw >= NN) return;
    int v = gw;
    int lane = threadIdx.x & 31;

    const uint2* __restrict__ gin = FINAL ? g_h1[side] : g_h0[side];
    const uint2* row = gin + (size_t)v * 64;
    float a[8] = {0, 0, 0, 0, 0, 0, 0, 0};
    unpack_add(a,     __ldg(row + lane));
    unpack_add(a + 4, __ldg(row + lane + 32));

    int s = g_rowptr[side][v];
    int e = g_rowptr[side][v + 1];
    const int* __restrict__ adj = g_adj[side];
    for (int p = s; p < e; p++) {
        int u = __ldg(adj + p);
        const uint2* ru = gin + (size_t)u * 64;
        uint2 x0 = __ldg(ru + lane);
        uint2 x1 = __ldg(ru + lane + 32);
        unpack_add(a,     x0);
        unpack_add(a + 4, x1);
    }

    float dv = g_dinv[side][v];
    if (!FINAL) {
        float r[8];
        #pragma unroll
        for (int k = 0; k < 8; k++) r[k] = fmaxf(dv * a[k], 0.f) * dv;
        uint2 o0, o1;
        o0.x = f2u(r[0], r[1]); o0.y = f2u(r[2], r[3]);
        o1.x = f2u(r[4], r[5]); o1.y = f2u(r[6], r[7]);
        uint2* o = g_h1[side] + (size_t)v * 64;
        o[lane]      = o0;
        o[lane + 32] = o1;
    } else {
        float r[8];
        float ss = 0.f;
        #pragma unroll
        for (int k = 0; k < 8; k++) { r[k] = dv * a[k]; ss += r[k] * r[k]; }
        #pragma unroll
        for (int off = 16; off; off >>= 1) ss += __shfl_xor_sync(0xffffffffu, ss, off);
        float inv = 1.0f / fmaxf(sqrtf(ss), 1e-12f);
        float4 r0, r1;
        r0.x = r[0] * inv; r0.y = r[1] * inv; r0.z = r[2] * inv; r0.w = r[3] * inv;
        r1.x = r[4] * inv; r1.y = r[5] * inv; r1.z = r[6] * inv; r1.w = r[7] * inv;
        size_t base = (size_t)(2 * SS) * D4 + (size_t)side * NN * D4 + (size_t)v * D4;
        out[base + lane]      = r0;
        out[base + lane + 32] = r1;
    }
}

// seed gather (copies rows out of d_out's ent regions into the seed regions)
__global__ void k_seed(const int* __restrict__ ssr, const int* __restrict__ stg,
                       float4* out) {
    int i = blockIdx.x * 256 + threadIdx.x;
    if (i >= 2 * SS * D4) return;
    int row = i >> 6, c = i & 63;
    int side = row >= SS;
    int s = row - side * SS;
    int node = side ? stg[s] : ssr[s];
    size_t src = (size_t)(2 * SS) * D4 + (size_t)side * NN * D4 + (size_t)node * D4 + c;
    out[i] = out[src];
}

// ---------------- launch ----------------
extern "C" void kernel_launch(void* const* d_in, const int* in_sizes, int n_in,
                              void* d_out, int out_size) {
    const float4* fsr = (const float4*)d_in[0];
    const float4* ftg = (const float4*)d_in[1];
    const int2*   esr = (const int2*)d_in[2];
    const int2*   etg = (const int2*)d_in[3];
    const int*    ssr = (const int*)d_in[4];
    const int*    stg = (const int*)d_in[5];
    float4* out = (float4*)d_out;

    k_zero<<<(2 * NN + 255) / 256, 256>>>();
    k_count<<<(2 * EE + 255) / 256, 256>>>(esr, etg);
    k_s1<<<2 * NT, 256>>>();
    k_s2<<<1, 2>>>();
    k_s3<<<2 * NT, 256>>>();
    k_fill<<<(2 * EE + 255) / 256, 256>>>(esr, etg);
    k_scale<<<(2 * NN * D4 + 255) / 256, 256>>>(fsr, ftg);

    // sides sequential on purpose: keeps each 51 MB fp16 gather table L2-resident
    int lb = (NN * 32 + 255) / 256;   // one warp per node
    k_layer<false><<<lb, 256>>>(0, nullptr);
    k_layer<false><<<lb, 256>>>(1, nullptr);
    k_layer<true><<<lb, 256>>>(0, out);
    k_layer<true><<<lb, 256>>>(1, out);

    k_seed<<<(2 * SS * D4 + 255) / 256, 256>>>(ssr, stg, out);
}